// round 4
// baseline (speedup 1.0000x reference)
#include <cuda_runtime.h>
#include <math.h>

#define T_TOK 4096
#define HDIM  1024
#define IDIM  2048
#define NEXP  8
#define NE    9      // 8 routed + 1 shared pseudo-expert

#define OFF_AUX 4194304
#define OFF_Z   4194305
#define OFF_LOG 4194306

// Scratch: 12288 rows (8192 routed pairs + 4096 shared) x IDIM fp32 activations
__device__ float g_act[12288 * 2048];
__device__ int   g_cnt[NEXP];
__device__ int   g_off[NEXP];
__device__ int   g_tok[NEXP * T_TOK];
__device__ float g_wt[NEXP * T_TOK];
__device__ float g_disp[NEXP];
__device__ float g_prob[NEXP];
__device__ float g_zsum;

// ---------------------------------------------------------------------------
__global__ void zero_misc_kernel() {
    int i = threadIdx.x;
    if (i < NEXP) { g_cnt[i] = 0; g_disp[i] = 0.f; g_prob[i] = 0.f; }
    if (i == 0) g_zsum = 0.f;
}

// ---------------------------------------------------------------------------
// One block (128 threads) per token: logits, softmax, top-2, list append,
// loss accumulators, write logits to out tail.
__global__ void router_kernel(const float* __restrict__ x,
                              const float* __restrict__ rw,
                              float* __restrict__ out) {
    int t = blockIdx.x;
    const float* xr = x + (size_t)t * HDIM;

    float acc[NEXP];
#pragma unroll
    for (int e = 0; e < NEXP; e++) acc[e] = 0.f;

    for (int h = threadIdx.x; h < HDIM; h += 128) {
        float xv = xr[h];
        const float4* w = (const float4*)(rw + (size_t)h * NEXP);
        float4 w0 = w[0], w1 = w[1];
        acc[0] += xv * w0.x; acc[1] += xv * w0.y;
        acc[2] += xv * w0.z; acc[3] += xv * w0.w;
        acc[4] += xv * w1.x; acc[5] += xv * w1.y;
        acc[6] += xv * w1.z; acc[7] += xv * w1.w;
    }

    __shared__ float red[128][NEXP];
    __shared__ float lg[NEXP];
#pragma unroll
    for (int e = 0; e < NEXP; e++) red[threadIdx.x][e] = acc[e];
    __syncthreads();

    if (threadIdx.x < NEXP) {
        float s = 0.f;
        for (int i = 0; i < 128; i++) s += red[i][threadIdx.x];
        lg[threadIdx.x] = s;
    }
    __syncthreads();

    if (threadIdx.x == 0) {
        float mx = lg[0];
#pragma unroll
        for (int e = 1; e < NEXP; e++) mx = fmaxf(mx, lg[e]);
        float p[NEXP]; float sum = 0.f;
#pragma unroll
        for (int e = 0; e < NEXP; e++) { p[e] = expf(lg[e] - mx); sum += p[e]; }
        float lse = mx + logf(sum);
        atomicAdd(&g_zsum, lse * lse);
        float inv = 1.f / sum;

        int i0 = 0; float b0 = -1.f;
#pragma unroll
        for (int e = 0; e < NEXP; e++) {
            p[e] *= inv;
            if (p[e] > b0) { b0 = p[e]; i0 = e; }
            atomicAdd(&g_prob[e], p[e]);
            out[OFF_LOG + (size_t)t * NEXP + e] = lg[e];
        }
        int i1 = -1; float b1 = -1.f;
#pragma unroll
        for (int e = 0; e < NEXP; e++) {
            if (e != i0 && p[e] > b1) { b1 = p[e]; i1 = e; }
        }
        float s2 = b0 + b1;
        float w0 = b0 / s2, w1 = b1 / s2;

        int s0 = atomicAdd(&g_cnt[i0], 1);
        g_tok[i0 * T_TOK + s0] = t; g_wt[i0 * T_TOK + s0] = w0;
        int s1 = atomicAdd(&g_cnt[i1], 1);
        g_tok[i1 * T_TOK + s1] = t; g_wt[i1 * T_TOK + s1] = w1;
        atomicAdd(&g_disp[i0], 0.5f);
        atomicAdd(&g_disp[i1], 0.5f);
    }
}

// ---------------------------------------------------------------------------
__global__ void offsets_kernel() {
    int o = 0;
    for (int e = 0; e < NEXP; e++) { g_off[e] = o; o += g_cnt[e]; }
}

// ---------------------------------------------------------------------------
// Pass A: act[row, 0:I] = silu(x @ gate_w[e]) * (x @ up_w[e]) for this
// expert's gathered token rows. 64x64x16 tiles, 4x4 microtile, 2 outputs.
__global__ __launch_bounds__(256) void gateup_kernel(
    const float* __restrict__ x,
    const float* __restrict__ gate_w, const float* __restrict__ up_w,
    const float* __restrict__ sgate_w, const float* __restrict__ sup_w) {
    int e = blockIdx.z;
    int cnt = (e < NEXP) ? g_cnt[e] : T_TOK;
    int row0 = blockIdx.y * 64;
    if (row0 >= cnt) return;
    int base = (e < NEXP) ? g_off[e] : 2 * T_TOK;
    int col0 = blockIdx.x * 64;
    const float* gw = (e < NEXP) ? gate_w + (size_t)e * HDIM * IDIM : sgate_w;
    const float* uw = (e < NEXP) ? up_w   + (size_t)e * HDIM * IDIM : sup_w;

    int tid = threadIdx.x;
    int tx = tid & 15, ty = tid >> 4;

    __shared__ float  As[16][65];
    __shared__ float4 Bg[16][16];
    __shared__ float4 Bu[16][16];
    __shared__ int    s_tok[64];

    if (tid < 64) {
        int r = row0 + tid;
        s_tok[tid] = (r < cnt) ? ((e < NEXP) ? g_tok[e * T_TOK + r] : r) : -1;
    }
    __syncthreads();

    float cg[4][4], cu[4][4];
#pragma unroll
    for (int i = 0; i < 4; i++)
#pragma unroll
        for (int j = 0; j < 4; j++) { cg[i][j] = 0.f; cu[i][j] = 0.f; }

    int ar = tid >> 2;     // local row 0..63
    int akq = tid & 3;     // k-quad
    int bh = tid >> 4;     // k row 0..15
    int biq = tid & 15;    // col quad

    int atok = s_tok[ar];
    const float* arow = x + (size_t)max(atok, 0) * HDIM;

    for (int k0 = 0; k0 < HDIM; k0 += 16) {
        float4 av = *(const float4*)(arow + k0 + akq * 4);
        if (atok < 0) av = make_float4(0.f, 0.f, 0.f, 0.f);
        As[akq * 4 + 0][ar] = av.x;
        As[akq * 4 + 1][ar] = av.y;
        As[akq * 4 + 2][ar] = av.z;
        As[akq * 4 + 3][ar] = av.w;
        Bg[bh][biq] = *(const float4*)(gw + (size_t)(k0 + bh) * IDIM + col0 + biq * 4);
        Bu[bh][biq] = *(const float4*)(uw + (size_t)(k0 + bh) * IDIM + col0 + biq * 4);
        __syncthreads();
#pragma unroll
        for (int kk = 0; kk < 16; kk++) {
            float a[4];
#pragma unroll
            for (int i = 0; i < 4; i++) a[i] = As[kk][ty * 4 + i];
            float4 bg = Bg[kk][tx];
            float4 bu = Bu[kk][tx];
#pragma unroll
            for (int i = 0; i < 4; i++) {
                cg[i][0] += a[i] * bg.x; cg[i][1] += a[i] * bg.y;
                cg[i][2] += a[i] * bg.z; cg[i][3] += a[i] * bg.w;
                cu[i][0] += a[i] * bu.x; cu[i][1] += a[i] * bu.y;
                cu[i][2] += a[i] * bu.z; cu[i][3] += a[i] * bu.w;
            }
        }
        __syncthreads();
    }

#pragma unroll
    for (int i = 0; i < 4; i++) {
        int r = ty * 4 + i;
        if (s_tok[r] < 0) continue;
        float4 v;
        float g0 = cg[i][0], g1 = cg[i][1], g2 = cg[i][2], g3 = cg[i][3];
        v.x = (g0 / (1.f + __expf(-g0))) * cu[i][0];
        v.y = (g1 / (1.f + __expf(-g1))) * cu[i][1];
        v.z = (g2 / (1.f + __expf(-g2))) * cu[i][2];
        v.w = (g3 / (1.f + __expf(-g3))) * cu[i][3];
        *(float4*)(g_act + (size_t)(base + row0 + r) * IDIM + col0 + tx * 4) = v;
    }
}

// ---------------------------------------------------------------------------
// Pass B: out[tok] += w_row * (act_row @ down_w[e])
__global__ __launch_bounds__(256) void down_kernel(
    const float* __restrict__ down_w, const float* __restrict__ sdown_w,
    float* __restrict__ out) {
    int e = blockIdx.z;
    int cnt = (e < NEXP) ? g_cnt[e] : T_TOK;
    int row0 = blockIdx.y * 64;
    if (row0 >= cnt) return;
    int base = (e < NEXP) ? g_off[e] : 2 * T_TOK;
    int col0 = blockIdx.x * 64;
    const float* dw = (e < NEXP) ? down_w + (size_t)e * IDIM * HDIM : sdown_w;

    int tid = threadIdx.x;
    int tx = tid & 15, ty = tid >> 4;

    __shared__ float  As[16][65];
    __shared__ float4 Bs[16][16];
    __shared__ int    s_tok[64];
    __shared__ float  s_w[64];

    if (tid < 64) {
        int r = row0 + tid;
        if (r < cnt) {
            s_tok[tid] = (e < NEXP) ? g_tok[e * T_TOK + r] : r;
            s_w[tid]   = (e < NEXP) ? g_wt[e * T_TOK + r] : 1.0f;
        } else s_tok[tid] = -1;
    }
    __syncthreads();

    float c[4][4];
#pragma unroll
    for (int i = 0; i < 4; i++)
#pragma unroll
        for (int j = 0; j < 4; j++) c[i][j] = 0.f;

    int ar = tid >> 2;
    int akq = tid & 3;
    int bh = tid >> 4;
    int biq = tid & 15;

    int arow_ok = (s_tok[ar] >= 0);
    const float* arow = g_act + (size_t)(arow_ok ? (base + row0 + ar) : 0) * IDIM;

    for (int k0 = 0; k0 < IDIM; k0 += 16) {
        float4 av = *(const float4*)(arow + k0 + akq * 4);
        As[akq * 4 + 0][ar] = av.x;
        As[akq * 4 + 1][ar] = av.y;
        As[akq * 4 + 2][ar] = av.z;
        As[akq * 4 + 3][ar] = av.w;
        Bs[bh][biq] = *(const float4*)(dw + (size_t)(k0 + bh) * HDIM + col0 + biq * 4);
        __syncthreads();
#pragma unroll
        for (int kk = 0; kk < 16; kk++) {
            float a[4];
#pragma unroll
            for (int i = 0; i < 4; i++) a[i] = As[kk][ty * 4 + i];
            float4 b = Bs[kk][tx];
#pragma unroll
            for (int i = 0; i < 4; i++) {
                c[i][0] += a[i] * b.x; c[i][1] += a[i] * b.y;
                c[i][2] += a[i] * b.z; c[i][3] += a[i] * b.w;
            }
        }
        __syncthreads();
    }

#pragma unroll
    for (int i = 0; i < 4; i++) {
        int r = ty * 4 + i;
        int tok = s_tok[r];
        if (tok < 0) continue;
        float w = s_w[r];
        float* dst = out + (size_t)tok * HDIM + col0 + tx * 4;
        atomicAdd(dst + 0, w * c[i][0]);
        atomicAdd(dst + 1, w * c[i][1]);
        atomicAdd(dst + 2, w * c[i][2]);
        atomicAdd(dst + 3, w * c[i][3]);
    }
}

// ---------------------------------------------------------------------------
__global__ void finalize_kernel(float* __restrict__ out) {
    if (threadIdx.x == 0) {
        float aux = 0.f;
        for (int e = 0; e < NEXP; e++)
            aux += (g_disp[e] / (float)T_TOK) * (g_prob[e] / (float)T_TOK);
        out[OFF_AUX] = (float)NEXP * aux;
        out[OFF_Z]   = g_zsum / (float)T_TOK;
    }
}

// ---------------------------------------------------------------------------
extern "C" void kernel_launch(void* const* d_in, const int* in_sizes, int n_in,
                              void* d_out, int out_size) {
    const float* x   = (const float*)d_in[0];
    const float* rw  = (const float*)d_in[1];
    const float* gw  = (const float*)d_in[2];
    const float* uw  = (const float*)d_in[3];
    const float* dw  = (const float*)d_in[4];
    const float* sgw = (const float*)d_in[5];
    const float* suw = (const float*)d_in[6];
    const float* sdw = (const float*)d_in[7];
    float* out = (float*)d_out;

    cudaMemsetAsync(out, 0, (size_t)4194304 * sizeof(float), 0);
    zero_misc_kernel<<<1, 32>>>();
    router_kernel<<<T_TOK, 128>>>(x, rw, out);
    offsets_kernel<<<1, 1>>>();
    gateup_kernel<<<dim3(IDIM / 64, T_TOK / 64, NE), 256>>>(x, gw, uw, sgw, suw);
    down_kernel<<<dim3(HDIM / 64, T_TOK / 64, NE), 256>>>(dw, sdw, out);
    finalize_kernel<<<1, 32>>>(out);
}

// round 10
// speedup vs baseline: 2.6150x; 2.6150x over previous
#include <cuda_runtime.h>
#include <cstdint>
#include <math.h>

#define T_TOK 4096
#define HDIM  1024
#define IDIM  2048
#define NEXP  8
#define NE    9      // 8 routed + 1 shared pseudo-expert

#define OFF_AUX 4194304
#define OFF_Z   4194305
#define OFF_LOG 4194306

// Scratch: 12288 rows (8192 routed pairs + 4096 shared) x IDIM fp32 activations
__device__ float g_act[12288 * 2048];
__device__ int   g_cnt[NEXP];
__device__ int   g_off[NEXP];
__device__ int   g_tok[NEXP * T_TOK];
__device__ float g_wt[NEXP * T_TOK];
__device__ float g_disp[NEXP];
__device__ float g_prob[NEXP];
__device__ float g_zsum;

// ---------------------------------------------------------------------------
__device__ __forceinline__ float to_tf32(float x) {
    uint32_t u; asm("cvt.rna.tf32.f32 %0, %1;" : "=r"(u) : "f"(x));
    return __uint_as_float(u);
}
__device__ __forceinline__ void cvt4(float4& v) {
    v.x = to_tf32(v.x); v.y = to_tf32(v.y); v.z = to_tf32(v.z); v.w = to_tf32(v.w);
}
// D += A(16x8) * B(8x8), tf32 inputs, f32 accum
__device__ __forceinline__ void mma8(float* d, const uint32_t* a, const uint32_t* b) {
    asm volatile(
        "mma.sync.aligned.m16n8k8.row.col.f32.tf32.tf32.f32 "
        "{%0,%1,%2,%3}, {%4,%5,%6,%7}, {%8,%9}, {%0,%1,%2,%3};"
        : "+f"(d[0]), "+f"(d[1]), "+f"(d[2]), "+f"(d[3])
        : "r"(a[0]), "r"(a[1]), "r"(a[2]), "r"(a[3]), "r"(b[0]), "r"(b[1]));
}
__device__ __forceinline__ uint32_t fb(float x) { return __float_as_uint(x); }

#define LDA 136   // 128 + 8 pad (floats) -> conflict-free fragment LDS
#define LDB 72    // 64 + 8 pad
#define LDD 136   // 128 + 8 pad

// ---------------------------------------------------------------------------
__global__ void zero_misc_kernel() {
    int i = threadIdx.x;
    if (i < NEXP) { g_cnt[i] = 0; g_disp[i] = 0.f; g_prob[i] = 0.f; }
    if (i == 0) g_zsum = 0.f;
}

// ---------------------------------------------------------------------------
__global__ void router_kernel(const float* __restrict__ x,
                              const float* __restrict__ rw,
                              float* __restrict__ out) {
    int t = blockIdx.x;
    const float* xr = x + (size_t)t * HDIM;

    float acc[NEXP];
#pragma unroll
    for (int e = 0; e < NEXP; e++) acc[e] = 0.f;

    for (int h = threadIdx.x; h < HDIM; h += 128) {
        float xv = xr[h];
        const float4* w = (const float4*)(rw + (size_t)h * NEXP);
        float4 w0 = w[0], w1 = w[1];
        acc[0] += xv * w0.x; acc[1] += xv * w0.y;
        acc[2] += xv * w0.z; acc[3] += xv * w0.w;
        acc[4] += xv * w1.x; acc[5] += xv * w1.y;
        acc[6] += xv * w1.z; acc[7] += xv * w1.w;
    }

    __shared__ float red[128][NEXP];
    __shared__ float lg[NEXP];
#pragma unroll
    for (int e = 0; e < NEXP; e++) red[threadIdx.x][e] = acc[e];
    __syncthreads();

    if (threadIdx.x < NEXP) {
        float s = 0.f;
        for (int i = 0; i < 128; i++) s += red[i][threadIdx.x];
        lg[threadIdx.x] = s;
    }
    __syncthreads();

    if (threadIdx.x == 0) {
        float mx = lg[0];
#pragma unroll
        for (int e = 1; e < NEXP; e++) mx = fmaxf(mx, lg[e]);
        float p[NEXP]; float sum = 0.f;
#pragma unroll
        for (int e = 0; e < NEXP; e++) { p[e] = expf(lg[e] - mx); sum += p[e]; }
        float lse = mx + logf(sum);
        atomicAdd(&g_zsum, lse * lse);
        float inv = 1.f / sum;

        int i0 = 0; float b0 = -1.f;
#pragma unroll
        for (int e = 0; e < NEXP; e++) {
            p[e] *= inv;
            if (p[e] > b0) { b0 = p[e]; i0 = e; }
            atomicAdd(&g_prob[e], p[e]);
            out[OFF_LOG + (size_t)t * NEXP + e] = lg[e];
        }
        int i1 = -1; float b1 = -1.f;
#pragma unroll
        for (int e = 0; e < NEXP; e++) {
            if (e != i0 && p[e] > b1) { b1 = p[e]; i1 = e; }
        }
        float s2 = b0 + b1;
        float w0 = b0 / s2, w1 = b1 / s2;

        int s0 = atomicAdd(&g_cnt[i0], 1);
        g_tok[i0 * T_TOK + s0] = t; g_wt[i0 * T_TOK + s0] = w0;
        int s1 = atomicAdd(&g_cnt[i1], 1);
        g_tok[i1 * T_TOK + s1] = t; g_wt[i1 * T_TOK + s1] = w1;
        atomicAdd(&g_disp[i0], 0.5f);
        atomicAdd(&g_disp[i1], 0.5f);
    }
}

__global__ void offsets_kernel() {
    int o = 0;
    for (int e = 0; e < NEXP; e++) { g_off[e] = o; o += g_cnt[e]; }
}

// ---------------------------------------------------------------------------
// Pass A: gate/up GEMM via tf32 mma.sync.
// Block tile M=128 (token rows), N=64 (intermediate cols), K=32.
// A tile stored transposed As[k][m] (LDA=136); B tiles Bg/Bu[k][n] (LDB=72).
// 8 warps: wm = w&3 (row 32*wm), wn = w>>2 (col 32*wn). Warp tile 32x32 per output.
__global__ __launch_bounds__(256) void gateup_mma_kernel(
    const float* __restrict__ x,
    const float* __restrict__ gate_w, const float* __restrict__ up_w,
    const float* __restrict__ sgate_w, const float* __restrict__ sup_w) {
    int e = blockIdx.z;
    int cnt = (e < NEXP) ? g_cnt[e] : T_TOK;
    int row0 = blockIdx.y * 128;
    if (row0 >= cnt) return;
    int base = (e < NEXP) ? g_off[e] : 2 * T_TOK;
    int n0 = blockIdx.x * 64;
    const float* gw = (e < NEXP) ? gate_w + (size_t)e * HDIM * IDIM : sgate_w;
    const float* uw = (e < NEXP) ? up_w   + (size_t)e * HDIM * IDIM : sup_w;

    extern __shared__ __align__(16) float smem[];
    // layout: [ As0 | Bg0 | Bu0 | As1 | Bg1 | Bu1 ]
    const int A_SZ = 32 * LDA;          // 4352 floats
    const int B_SZ = 32 * LDB;          // 2304 floats
    const int STG  = A_SZ + 2 * B_SZ;   // 8960 floats per stage

    __shared__ int s_tok[128];

    int tid = threadIdx.x;
    int w = tid >> 5, lane = tid & 31;
    int g = lane >> 2, tig = lane & 3;
    int wm = w & 3, wn = w >> 2;

    if (tid < 128) {
        int r = row0 + tid;
        s_tok[tid] = (r < cnt) ? ((e < NEXP) ? g_tok[e * T_TOK + r] : r) : -1;
    }
    __syncthreads();

    // staging indices
    int sm = tid >> 1;            // row 0..127 (A)
    int skh = (tid & 1) * 16;     // k half
    const float* arow = x + (size_t)max(s_tok[sm], 0) * HDIM;
    int bq0 = tid, bq1 = tid + 256;          // B float4 ids (512 total per matrix)

    float4 ra[4], rg0, rg1, ru0, ru1;

    auto ldg = [&](int c) {
        int k0 = c * 32;
#pragma unroll
        for (int i = 0; i < 4; i++) {
            ra[i] = *(const float4*)(arow + k0 + skh + i * 4);
            cvt4(ra[i]);
        }
        int r0 = bq0 >> 4, c0 = (bq0 & 15) * 4;
        int r1 = bq1 >> 4, c1 = (bq1 & 15) * 4;
        rg0 = *(const float4*)(gw + (size_t)(k0 + r0) * IDIM + n0 + c0); cvt4(rg0);
        rg1 = *(const float4*)(gw + (size_t)(k0 + r1) * IDIM + n0 + c1); cvt4(rg1);
        ru0 = *(const float4*)(uw + (size_t)(k0 + r0) * IDIM + n0 + c0); cvt4(ru0);
        ru1 = *(const float4*)(uw + (size_t)(k0 + r1) * IDIM + n0 + c1); cvt4(ru1);
    };
    auto sts = [&](int b) {
        float* As = smem + b * STG;
        float* Bg = As + A_SZ;
        float* Bu = Bg + B_SZ;
#pragma unroll
        for (int i = 0; i < 4; i++) {
            As[(skh + i * 4 + 0) * LDA + sm] = ra[i].x;
            As[(skh + i * 4 + 1) * LDA + sm] = ra[i].y;
            As[(skh + i * 4 + 2) * LDA + sm] = ra[i].z;
            As[(skh + i * 4 + 3) * LDA + sm] = ra[i].w;
        }
        int r0 = bq0 >> 4, c0 = (bq0 & 15) * 4;
        int r1 = bq1 >> 4, c1 = (bq1 & 15) * 4;
        *(float4*)(Bg + r0 * LDB + c0) = rg0;
        *(float4*)(Bg + r1 * LDB + c1) = rg1;
        *(float4*)(Bu + r0 * LDB + c0) = ru0;
        *(float4*)(Bu + r1 * LDB + c1) = ru1;
    };

    float cg[2][4][4], cu[2][4][4];
#pragma unroll
    for (int mi = 0; mi < 2; mi++)
#pragma unroll
        for (int j = 0; j < 4; j++)
#pragma unroll
            for (int q = 0; q < 4; q++) { cg[mi][j][q] = 0.f; cu[mi][j][q] = 0.f; }

    const int NK = HDIM / 32;  // 32
    ldg(0); sts(0); __syncthreads();
    ldg(1);

    for (int c = 0; c < NK; c++) {
        int b = c & 1;
        if (c + 1 < NK) sts(b ^ 1);
        __syncthreads();
        if (c + 2 < NK) ldg(c + 2);

        const float* As = smem + b * STG;
        const float* Bg = As + A_SZ;
        const float* Bu = Bg + B_SZ;
#pragma unroll
        for (int kq = 0; kq < 4; kq++) {
            int kk = kq * 8;
            uint32_t a[2][4];
#pragma unroll
            for (int mi = 0; mi < 2; mi++) {
                int m0 = wm * 32 + mi * 16;
                a[mi][0] = fb(As[(kk + tig) * LDA + m0 + g]);
                a[mi][1] = fb(As[(kk + tig) * LDA + m0 + 8 + g]);
                a[mi][2] = fb(As[(kk + 4 + tig) * LDA + m0 + g]);
                a[mi][3] = fb(As[(kk + 4 + tig) * LDA + m0 + 8 + g]);
            }
            uint32_t bg[4][2], bu[4][2];
#pragma unroll
            for (int j = 0; j < 4; j++) {
                int n = wn * 32 + j * 8 + g;
                bg[j][0] = fb(Bg[(kk + tig) * LDB + n]);
                bg[j][1] = fb(Bg[(kk + 4 + tig) * LDB + n]);
                bu[j][0] = fb(Bu[(kk + tig) * LDB + n]);
                bu[j][1] = fb(Bu[(kk + 4 + tig) * LDB + n]);
            }
#pragma unroll
            for (int mi = 0; mi < 2; mi++)
#pragma unroll
                for (int j = 0; j < 4; j++) {
                    mma8(cg[mi][j], a[mi], bg[j]);
                    mma8(cu[mi][j], a[mi], bu[j]);
                }
        }
        __syncthreads();
    }

    // Epilogue: silu(gate)*up -> g_act
#pragma unroll
    for (int mi = 0; mi < 2; mi++) {
#pragma unroll
        for (int half = 0; half < 2; half++) {
            int r = wm * 32 + mi * 16 + half * 8 + g;
            if (s_tok[r] < 0) continue;
            float* dst = g_act + (size_t)(base + row0 + r) * IDIM + n0 + wn * 32 + 2 * tig;
#pragma unroll
            for (int j = 0; j < 4; j++) {
                float gv0 = cg[mi][j][half * 2 + 0], uv0 = cu[mi][j][half * 2 + 0];
                float gv1 = cg[mi][j][half * 2 + 1], uv1 = cu[mi][j][half * 2 + 1];
                float2 v;
                v.x = (gv0 / (1.f + __expf(-gv0))) * uv0;
                v.y = (gv1 / (1.f + __expf(-gv1))) * uv1;
                *(float2*)(dst + j * 8) = v;
            }
        }
    }
}

// ---------------------------------------------------------------------------
// Pass B: out[tok] += w * (act_row @ down_w). Block tile M=128, N=128, K=32.
// 8 warps: wm = w&3 (row 32*wm), wn = w>>2 (col 64*wn). Warp tile 32x64.
__global__ __launch_bounds__(256) void down_mma_kernel(
    const float* __restrict__ down_w, const float* __restrict__ sdown_w,
    float* __restrict__ out) {
    int e = blockIdx.z;
    int cnt = (e < NEXP) ? g_cnt[e] : T_TOK;
    int row0 = blockIdx.y * 128;
    if (row0 >= cnt) return;
    int base = (e < NEXP) ? g_off[e] : 2 * T_TOK;
    int n0 = blockIdx.x * 128;
    const float* dw = (e < NEXP) ? down_w + (size_t)e * IDIM * HDIM : sdown_w;

    extern __shared__ __align__(16) float smem[];
    const int A_SZ = 32 * LDA;
    const int B_SZ = 32 * LDD;
    const int STG  = A_SZ + B_SZ;       // 8704 floats

    __shared__ int   s_tok[128];
    __shared__ float s_w[128];

    int tid = threadIdx.x;
    int w = tid >> 5, lane = tid & 31;
    int g = lane >> 2, tig = lane & 3;
    int wm = w & 3, wn = w >> 2;

    if (tid < 128) {
        int r = row0 + tid;
        if (r < cnt) {
            s_tok[tid] = (e < NEXP) ? g_tok[e * T_TOK + r] : r;
            s_w[tid]   = (e < NEXP) ? g_wt[e * T_TOK + r] : 1.0f;
        } else { s_tok[tid] = -1; s_w[tid] = 0.f; }
    }
    __syncthreads();

    int sm = tid >> 1;
    int skh = (tid & 1) * 16;
    int arow_i = (row0 + sm < cnt) ? (base + row0 + sm) : base;
    const float* arow = g_act + (size_t)arow_i * IDIM;

    float4 ra[4], rb[4];

    auto ldg = [&](int c) {
        int k0 = c * 32;
#pragma unroll
        for (int i = 0; i < 4; i++) {
            ra[i] = *(const float4*)(arow + k0 + skh + i * 4);
            cvt4(ra[i]);
        }
#pragma unroll
        for (int i = 0; i < 4; i++) {
            int q = tid + i * 256;              // 0..1023
            int r = q >> 5, c4 = (q & 31) * 4;
            rb[i] = *(const float4*)(dw + (size_t)(k0 + r) * HDIM + n0 + c4);
            cvt4(rb[i]);
        }
    };
    auto sts = [&](int b) {
        float* As = smem + b * STG;
        float* Bs = As + A_SZ;
#pragma unroll
        for (int i = 0; i < 4; i++) {
            As[(skh + i * 4 + 0) * LDA + sm] = ra[i].x;
            As[(skh + i * 4 + 1) * LDA + sm] = ra[i].y;
            As[(skh + i * 4 + 2) * LDA + sm] = ra[i].z;
            As[(skh + i * 4 + 3) * LDA + sm] = ra[i].w;
        }
#pragma unroll
        for (int i = 0; i < 4; i++) {
            int q = tid + i * 256;
            int r = q >> 5, c4 = (q & 31) * 4;
            *(float4*)(Bs + r * LDD + c4) = rb[i];
        }
    };

    float acc[2][8][4];
#pragma unroll
    for (int mi = 0; mi < 2; mi++)
#pragma unroll
        for (int j = 0; j < 8; j++)
#pragma unroll
            for (int q = 0; q < 4; q++) acc[mi][j][q] = 0.f;

    const int NK = IDIM / 32;  // 64
    ldg(0); sts(0); __syncthreads();
    ldg(1);

    for (int c = 0; c < NK; c++) {
        int b = c & 1;
        if (c + 1 < NK) sts(b ^ 1);
        __syncthreads();
        if (c + 2 < NK) ldg(c + 2);

        const float* As = smem + b * STG;
        const float* Bs = As + A_SZ;
#pragma unroll
        for (int kq = 0; kq < 4; kq++) {
            int kk = kq * 8;
            uint32_t a[2][4];
#pragma unroll
            for (int mi = 0; mi < 2; mi++) {
                int m0 = wm * 32 + mi * 16;
                a[mi][0] = fb(As[(kk + tig) * LDA + m0 + g]);
                a[mi][1] = fb(As[(kk + tig) * LDA + m0 + 8 + g]);
                a[mi][2] = fb(As[(kk + 4 + tig) * LDA + m0 + g]);
                a[mi][3] = fb(As[(kk + 4 + tig) * LDA + m0 + 8 + g]);
            }
            uint32_t bf[8][2];
#pragma unroll
            for (int j = 0; j < 8; j++) {
                int n = wn * 64 + j * 8 + g;
                bf[j][0] = fb(Bs[(kk + tig) * LDD + n]);
                bf[j][1] = fb(Bs[(kk + 4 + tig) * LDD + n]);
            }
#pragma unroll
            for (int mi = 0; mi < 2; mi++)
#pragma unroll
                for (int j = 0; j < 8; j++)
                    mma8(acc[mi][j], a[mi], bf[j]);
        }
        __syncthreads();
    }

    // Epilogue: scale by router weight, atomicAdd into out
#pragma unroll
    for (int mi = 0; mi < 2; mi++) {
#pragma unroll
        for (int half = 0; half < 2; half++) {
            int r = wm * 32 + mi * 16 + half * 8 + g;
            int tok = s_tok[r];
            if (tok < 0) continue;
            float wr = s_w[r];
            float* dst = out + (size_t)tok * HDIM + n0 + wn * 64 + 2 * tig;
#pragma unroll
            for (int j = 0; j < 8; j++) {
                atomicAdd(dst + j * 8 + 0, wr * acc[mi][j][half * 2 + 0]);
                atomicAdd(dst + j * 8 + 1, wr * acc[mi][j][half * 2 + 1]);
            }
        }
    }
}

// ---------------------------------------------------------------------------
__global__ void finalize_kernel(float* __restrict__ out) {
    if (threadIdx.x == 0) {
        float aux = 0.f;
        for (int e = 0; e < NEXP; e++)
            aux += (g_disp[e] / (float)T_TOK) * (g_prob[e] / (float)T_TOK);
        out[OFF_AUX] = (float)NEXP * aux;
        out[OFF_Z]   = g_zsum / (float)T_TOK;
    }
}

// ---------------------------------------------------------------------------
#define SMEM_GATEUP (2 * (32 * LDA + 2 * 32 * LDB) * 4)   // 71680 B
#define SMEM_DOWN   (2 * (32 * LDA + 32 * LDD) * 4)       // 69632 B

extern "C" void kernel_launch(void* const* d_in, const int* in_sizes, int n_in,
                              void* d_out, int out_size) {
    const float* x   = (const float*)d_in[0];
    const float* rw  = (const float*)d_in[1];
    const float* gw  = (const float*)d_in[2];
    const float* uw  = (const float*)d_in[3];
    const float* dw  = (const float*)d_in[4];
    const float* sgw = (const float*)d_in[5];
    const float* suw = (const float*)d_in[6];
    const float* sdw = (const float*)d_in[7];
    float* out = (float*)d_out;

    cudaFuncSetAttribute(gateup_mma_kernel,
                         cudaFuncAttributeMaxDynamicSharedMemorySize, SMEM_GATEUP);
    cudaFuncSetAttribute(down_mma_kernel,
                         cudaFuncAttributeMaxDynamicSharedMemorySize, SMEM_DOWN);

    cudaMemsetAsync(out, 0, (size_t)4194304 * sizeof(float), 0);
    zero_misc_kernel<<<1, 32>>>();
    router_kernel<<<T_TOK, 128>>>(x, rw, out);
    offsets_kernel<<<1, 1>>>();
    gateup_mma_kernel<<<dim3(IDIM / 64, T_TOK / 128, NE), 256, SMEM_GATEUP>>>(
        x, gw, uw, sgw, suw);
    down_mma_kernel<<<dim3(HDIM / 128, T_TOK / 128, NE), 256, SMEM_DOWN>>>(dw, sdw, out);
    finalize_kernel<<<1, 32>>>(out);
}